// round 10
// baseline (speedup 1.0000x reference)
#include <cuda_runtime.h>
#include <cstdint>
#include <cstddef>

namespace {

constexpr int BATCH = 4096;
constexpr int FEAT  = 832;          // 64 * (1+3+9)
constexpr int NB    = 32;           // batch tile per block
constexpr int NBLK  = BATCH / NB;   // 128 blocks
constexpr int NTHR  = 256;
constexpr int WSZ   = 64 * 64 * 64; // weights per path

// path tables: (L1, L2, Lout) in reference enumeration order
constexpr int P_L1[15]   = {0,0,0,1,1,1,1,1,1,2,2,2,2,2,2};
constexpr int P_L2[15]   = {0,1,2,0,1,1,1,2,2,0,1,1,2,2,2};
constexpr int P_LOUT[15] = {0,1,2,1,2,0,1,1,2,2,1,2,2,0,1};

constexpr int OFFS[3]  = {0, 64, 256};  // feature offset of L-block
constexpr int SLOTB[3] = {0, 1, 4};     // out slot base per Lout
constexpr int R_[3]    = {1, 3, 9};     // 3^L

// smem layout (floats)
constexpr int SZ_OUT = 64 * 13 * NB;    // 26624  out accumulators [c][slot][n]
constexpr int SZ_B2  = 576 * 16 * 2;    // 18432  B block as f32x2 pairs [f][np]
constexpr int SZ_W2  = 64 * 65 * 2;     // 8320   W chunk duplicated (w,w) [c][b], stride-65 pad
constexpr int SZ_A2  = 9 * 16 * 2;      // 288    A chunk as pairs [sA][np]
constexpr int SMEM_FLOATS = SZ_OUT + SZ_B2 + SZ_W2 + SZ_A2;   // 53664
constexpr int SMEM_BYTES  = SMEM_FLOATS * 4;                  // 214656

// ---------------- packed f32x2 primitives (sm_103a) ----------------
struct f2 { unsigned long long v; };

__device__ __forceinline__ f2 fmul2(f2 a, f2 b) {
    f2 r; asm("mul.rn.f32x2 %0, %1, %2;" : "=l"(r.v) : "l"(a.v), "l"(b.v)); return r;
}
__device__ __forceinline__ f2 ffma2(f2 a, f2 b, f2 c) {
    f2 r; asm("fma.rn.f32x2 %0, %1, %2, %3;" : "=l"(r.v) : "l"(a.v), "l"(b.v), "l"(c.v)); return r;
}
__device__ __forceinline__ f2 fadd2(f2 a, f2 b) {
    f2 r; asm("add.rn.f32x2 %0, %1, %2;" : "=l"(r.v) : "l"(a.v), "l"(b.v)); return r;
}
__device__ __forceinline__ f2 fneg2(f2 a) {
    a.v ^= 0x8000000080000000ULL; return a;
}
__device__ __forceinline__ f2 fzero2() { f2 r; r.v = 0ULL; return r; }

__device__ __forceinline__ unsigned long long pack2(float x, float y) {
    unsigned long long r; asm("mov.b64 %0, {%1, %2};" : "=l"(r) : "f"(x), "f"(y)); return r;
}
__device__ __forceinline__ f2 ld2(const float* p) {
    f2 r; r.v = *reinterpret_cast<const unsigned long long*>(p); return r;
}
__device__ __forceinline__ void unpack2(f2 a, float& lo, float& hi) {
    unsigned int l, h;
    asm("mov.b64 {%0, %1}, %2;" : "=r"(l), "=r"(h) : "l"(a.v));
    lo = __uint_as_float(l); hi = __uint_as_float(h);
}

// ---- spatial pair-product per path (f32x2 lanes = 2 batch elements) ----
template<int P>
__device__ __forceinline__ void compute_pvals(const f2* a, const f2* b, f2* pv) {
    if constexpr (P == 0) {            // (0,0,0)
        pv[0] = fmul2(a[0], b[0]);
    } else if constexpr (P == 1) {     // (0,1,1)
        pv[0] = fmul2(a[0], b[0]); pv[1] = fmul2(a[0], b[1]); pv[2] = fmul2(a[0], b[2]);
    } else if constexpr (P == 2) {     // (0,2,2)
        #pragma unroll
        for (int s = 0; s < 9; ++s) pv[s] = fmul2(a[0], b[s]);
    } else if constexpr (P == 3) {     // (1,0,1)
        pv[0] = fmul2(a[0], b[0]); pv[1] = fmul2(a[1], b[0]); pv[2] = fmul2(a[2], b[0]);
    } else if constexpr (P == 4) {     // (1,1,2): outer product
        #pragma unroll
        for (int i = 0; i < 3; ++i)
            #pragma unroll
            for (int j = 0; j < 3; ++j) pv[i*3+j] = fmul2(a[i], b[j]);
    } else if constexpr (P == 5) {     // (1,1,0): dot
        pv[0] = ffma2(a[2], b[2], ffma2(a[1], b[1], fmul2(a[0], b[0])));
    } else if constexpr (P == 6) {     // (1,1,1,eps): cross(a,b)
        pv[0] = ffma2(a[1], b[2], fneg2(fmul2(a[2], b[1])));
        pv[1] = ffma2(a[2], b[0], fneg2(fmul2(a[0], b[2])));
        pv[2] = ffma2(a[0], b[1], fneg2(fmul2(a[1], b[0])));
    } else if constexpr (P == 7) {     // (1,2,1)
        #pragma unroll
        for (int e = 0; e < 3; ++e)
            pv[e] = ffma2(a[2], b[e*3+2], ffma2(a[1], b[e*3+1], fmul2(a[0], b[e*3+0])));
    } else if constexpr (P == 8) {     // (1,2,2,eps): cross(a, B2[e,:])
        #pragma unroll
        for (int e = 0; e < 3; ++e) {
            const f2* be = b + e*3;
            pv[e*3+0] = ffma2(a[1], be[2], fneg2(fmul2(a[2], be[1])));
            pv[e*3+1] = ffma2(a[2], be[0], fneg2(fmul2(a[0], be[2])));
            pv[e*3+2] = ffma2(a[0], be[1], fneg2(fmul2(a[1], be[0])));
        }
    } else if constexpr (P == 9) {     // (2,0,2)
        #pragma unroll
        for (int s = 0; s < 9; ++s) pv[s] = fmul2(a[s], b[0]);
    } else if constexpr (P == 10) {    // (2,1,1)
        #pragma unroll
        for (int d = 0; d < 3; ++d)
            pv[d] = ffma2(a[d*3+2], b[2], ffma2(a[d*3+1], b[1], fmul2(a[d*3+0], b[0])));
    } else if constexpr (P == 11) {    // (2,1,2,eps): cross(A2[d,:], b)
        #pragma unroll
        for (int d = 0; d < 3; ++d) {
            const f2* ad = a + d*3;
            pv[d*3+0] = ffma2(ad[1], b[2], fneg2(fmul2(ad[2], b[1])));
            pv[d*3+1] = ffma2(ad[2], b[0], fneg2(fmul2(ad[0], b[2])));
            pv[d*3+2] = ffma2(ad[0], b[1], fneg2(fmul2(ad[1], b[0])));
        }
    } else if constexpr (P == 12) {    // (2,2,2)
        #pragma unroll
        for (int d = 0; d < 3; ++d)
            #pragma unroll
            for (int f = 0; f < 3; ++f)
                pv[d*3+f] = ffma2(a[d*3+2], b[f*3+2],
                            ffma2(a[d*3+1], b[f*3+1], fmul2(a[d*3+0], b[f*3+0])));
    } else if constexpr (P == 13) {    // (2,2,0): full contraction
        f2 s = fmul2(a[0], b[0]);
        #pragma unroll
        for (int t = 1; t < 9; ++t) s = ffma2(a[t], b[t], s);
        pv[0] = s;
    } else {                           // P==14 (2,2,1,eps)
        f2 M[3][3];
        #pragma unroll
        for (int d = 0; d < 3; ++d)
            #pragma unroll
            for (int f = 0; f < 3; ++f)
                M[d][f] = ffma2(a[d*3+2], b[f*3+2],
                          ffma2(a[d*3+1], b[f*3+1], fmul2(a[d*3+0], b[f*3+0])));
        pv[0] = fadd2(M[1][2], fneg2(M[2][1]));
        pv[1] = fadd2(M[2][0], fneg2(M[0][2]));
        pv[2] = fadd2(M[0][1], fneg2(M[1][0]));
    }
}

template<int P>
__device__ __forceinline__ void run_path(
    const float* __restrict__ x1, const float* __restrict__ x2,
    const float* __restrict__ w, int n0,
    float* __restrict__ sOut, float* __restrict__ sB,
    float* __restrict__ sW, float* __restrict__ sA,
    int tid, int cg, int nh)
{
    constexpr int L1 = P_L1[P], L2 = P_L2[P], LO = P_LOUT[P];
    constexpr int R1 = R_[L1], R2 = R_[L2], RO = R_[LO];
    constexpr int OFF1 = OFFS[L1], OFF2 = OFFS[L2];
    constexpr int SLOT = SLOTB[LO];
    constexpr int NF = 64 * R2;           // B-block features
    const float* wp = w + (size_t)P * WSZ;

    // entry barrier: previous path finished reading sB
    __syncthreads();

    // stage B block as packed n-pairs: sB2[f][np] = (x2[2np, f], x2[2np+1, f])
    for (int idx = tid; idx < NF * 16; idx += NTHR) {
        int np = idx / NF;
        int f  = idx - np * NF;
        const float* src = x2 + (size_t)(n0 + 2*np) * FEAT + OFF2 + f;
        *reinterpret_cast<unsigned long long*>(sB + (f * 16 + np) * 2)
            = pack2(src[0], src[FEAT]);
    }

    f2 acc[4][RO];
    #pragma unroll
    for (int cc = 0; cc < 4; ++cc)
        #pragma unroll
        for (int o = 0; o < RO; ++o) acc[cc][o] = fzero2();

    for (int a = 0; a < 64; ++a) {
        __syncthreads();  // prior chunk's sW/sA reads done (and at a=0: sB stores visible)
        // stage W chunk for this a, duplicated (w,w): sW2[c*65+b]
        {
            int c = tid >> 2, q = tid & 3;
            const float* src = wp + (size_t)c * 4096 + (size_t)a * 64 + q * 16;
            float4 v0 = reinterpret_cast<const float4*>(src)[0];
            float4 v1 = reinterpret_cast<const float4*>(src)[1];
            float4 v2 = reinterpret_cast<const float4*>(src)[2];
            float4 v3 = reinterpret_cast<const float4*>(src)[3];
            float buf[16] = {v0.x,v0.y,v0.z,v0.w, v1.x,v1.y,v1.z,v1.w,
                             v2.x,v2.y,v2.z,v2.w, v3.x,v3.y,v3.z,v3.w};
            unsigned long long* dst =
                reinterpret_cast<unsigned long long*>(sW + (c * 65 + q * 16) * 2);
            #pragma unroll
            for (int j = 0; j < 16; ++j) dst[j] = pack2(buf[j], buf[j]);
        }
        // stage A chunk as pairs: sA2[s][np]
        {
            int idx = tid;
            if (idx < 16 * R1) {
                int s = idx >> 4, np = idx & 15;
                const float* src = x1 + (size_t)(n0 + 2*np) * FEAT + OFF1 + a * R1 + s;
                *reinterpret_cast<unsigned long long*>(sA + (s * 16 + np) * 2)
                    = pack2(src[0], src[FEAT]);
            }
        }
        __syncthreads();

        f2 areg[R1];
        #pragma unroll
        for (int s = 0; s < R1; ++s) areg[s] = ld2(sA + (s * 16 + nh) * 2);

        #pragma unroll 4
        for (int b = 0; b < 64; ++b) {
            f2 breg[R2];
            #pragma unroll
            for (int s = 0; s < R2; ++s) breg[s] = ld2(sB + ((b * R2 + s) * 16 + nh) * 2);
            f2 pv[RO];
            compute_pvals<P>(areg, breg, pv);
            #pragma unroll
            for (int cc = 0; cc < 4; ++cc) {
                f2 wv = ld2(sW + ((cg * 4 + cc) * 65 + b) * 2);  // (w,w) broadcast
                #pragma unroll
                for (int o = 0; o < RO; ++o)
                    acc[cc][o] = ffma2(wv, pv[o], acc[cc][o]);
            }
        }
    }

    // merge into smem out accumulators (owner-exclusive (c, n-pair) -> no races)
    #pragma unroll
    for (int cc = 0; cc < 4; ++cc) {
        int c = cg * 4 + cc;
        #pragma unroll
        for (int o = 0; o < RO; ++o) {
            float lo, hi;
            unpack2(acc[cc][o], lo, hi);
            float* p = sOut + (c * 13 + SLOT + o) * NB + 2 * nh;
            p[0] += lo;
            p[1] += hi;
        }
    }
}

__global__ void __launch_bounds__(NTHR, 1)
tp_kernel(const float* __restrict__ x1, const float* __restrict__ x2,
          const float* __restrict__ w, float* __restrict__ out)
{
    extern __shared__ float smem[];
    float* sOut = smem;
    float* sB   = sOut + SZ_OUT;
    float* sW   = sB + SZ_B2;
    float* sA   = sW + SZ_W2;

    const int tid = threadIdx.x;
    const int n0  = blockIdx.x * NB;
    // c-group: 16 groups of 4 channels; each warp splits into two chalf groups
    const int cg  = ((tid >> 5) << 1) | ((tid >> 4) & 1);
    const int nh  = tid & 15;   // n-pair lane: owns batch elems (2nh, 2nh+1)

    for (int i = tid; i < SZ_OUT; i += NTHR) sOut[i] = 0.f;

    run_path< 0>(x1,x2,w,n0,sOut,sB,sW,sA,tid,cg,nh);
    run_path< 1>(x1,x2,w,n0,sOut,sB,sW,sA,tid,cg,nh);
    run_path< 2>(x1,x2,w,n0,sOut,sB,sW,sA,tid,cg,nh);
    run_path< 3>(x1,x2,w,n0,sOut,sB,sW,sA,tid,cg,nh);
    run_path< 4>(x1,x2,w,n0,sOut,sB,sW,sA,tid,cg,nh);
    run_path< 5>(x1,x2,w,n0,sOut,sB,sW,sA,tid,cg,nh);
    run_path< 6>(x1,x2,w,n0,sOut,sB,sW,sA,tid,cg,nh);
    run_path< 7>(x1,x2,w,n0,sOut,sB,sW,sA,tid,cg,nh);
    run_path< 8>(x1,x2,w,n0,sOut,sB,sW,sA,tid,cg,nh);
    run_path< 9>(x1,x2,w,n0,sOut,sB,sW,sA,tid,cg,nh);
    run_path<10>(x1,x2,w,n0,sOut,sB,sW,sA,tid,cg,nh);
    run_path<11>(x1,x2,w,n0,sOut,sB,sW,sA,tid,cg,nh);
    run_path<12>(x1,x2,w,n0,sOut,sB,sW,sA,tid,cg,nh);
    run_path<13>(x1,x2,w,n0,sOut,sB,sW,sA,tid,cg,nh);
    run_path<14>(x1,x2,w,n0,sOut,sB,sW,sA,tid,cg,nh);

    __syncthreads();
    // coalesced writeback: out[n, f], f -> (c, slot)
    for (int i = tid; i < NB * FEAT; i += NTHR) {
        int n = i / FEAT;
        int f = i - n * FEAT;
        int c, slot;
        if (f < 64)       { c = f;                slot = 0; }
        else if (f < 256) { int r = f - 64;  c = r / 3; slot = 1 + (r - c * 3); }
        else              { int r = f - 256; c = r / 9; slot = 4 + (r - c * 9); }
        out[(size_t)(blockIdx.x * NB + n) * FEAT + f] = sOut[(c * 13 + slot) * NB + n];
    }
}

} // namespace

extern "C" void kernel_launch(void* const* d_in, const int* in_sizes, int n_in,
                              void* d_out, int out_size)
{
    const float* x1 = (const float*)d_in[0];
    const float* x2 = (const float*)d_in[1];
    const float* w  = (const float*)d_in[2];
    float* out = (float*)d_out;

    cudaFuncSetAttribute(tp_kernel, cudaFuncAttributeMaxDynamicSharedMemorySize, SMEM_BYTES);
    tp_kernel<<<NBLK, NTHR, SMEM_BYTES>>>(x1, x2, w, out);
}

// round 13
// speedup vs baseline: 1.0038x; 1.0038x over previous
#include <cuda_runtime.h>
#include <cstdint>
#include <cstddef>

namespace {

constexpr int BATCH = 4096;
constexpr int FEAT  = 832;          // 64 * (1+3+9)
constexpr int NB    = 32;           // batch tile per block
constexpr int NBLK  = BATCH / NB;   // 128 blocks
constexpr int NTHR  = 256;
constexpr int WSZ   = 64 * 64 * 64; // weights per path

// path tables: (L1, L2, Lout) in reference enumeration order
constexpr int P_L1[15]   = {0,0,0,1,1,1,1,1,1,2,2,2,2,2,2};
constexpr int P_L2[15]   = {0,1,2,0,1,1,1,2,2,0,1,1,2,2,2};
constexpr int P_LOUT[15] = {0,1,2,1,2,0,1,1,2,2,1,2,2,0,1};

constexpr int OFFS[3]  = {0, 64, 256};  // feature offset of L-block
constexpr int SLOTB[3] = {0, 1, 4};     // out slot base per Lout
constexpr int R_[3]    = {1, 3, 9};     // 3^L

// smem layout (floats)
constexpr int SZ_OUT = 64 * 13 * NB;    // 26624  out accumulators [c][slot][n]
constexpr int SZ_B2  = 576 * 16 * 2;    // 18432  B block as f32x2 pairs [f][np]
constexpr int SZ_W2  = 64 * 65 * 2;     // 8320   W chunk duplicated (w,w) [c][b], stride-65 pad
constexpr int SZ_A2  = 9 * 16 * 2;      // 288    A chunk as pairs [sA][np]
constexpr int SMEM_FLOATS = SZ_OUT + SZ_B2 + SZ_W2 + SZ_A2;   // 53664
constexpr int SMEM_BYTES  = SMEM_FLOATS * 4;                  // 214656

// ---------------- packed f32x2 primitives (sm_103a) ----------------
struct f2 { unsigned long long v; };

__device__ __forceinline__ f2 fmul2(f2 a, f2 b) {
    f2 r; asm("mul.rn.f32x2 %0, %1, %2;" : "=l"(r.v) : "l"(a.v), "l"(b.v)); return r;
}
__device__ __forceinline__ f2 ffma2(f2 a, f2 b, f2 c) {
    f2 r; asm("fma.rn.f32x2 %0, %1, %2, %3;" : "=l"(r.v) : "l"(a.v), "l"(b.v), "l"(c.v)); return r;
}
__device__ __forceinline__ f2 fadd2(f2 a, f2 b) {
    f2 r; asm("add.rn.f32x2 %0, %1, %2;" : "=l"(r.v) : "l"(a.v), "l"(b.v)); return r;
}
__device__ __forceinline__ f2 fneg2(f2 a) {
    a.v ^= 0x8000000080000000ULL; return a;
}
__device__ __forceinline__ f2 fzero2() { f2 r; r.v = 0ULL; return r; }

__device__ __forceinline__ unsigned long long pack2(float x, float y) {
    unsigned long long r; asm("mov.b64 %0, {%1, %2};" : "=l"(r) : "f"(x), "f"(y)); return r;
}
__device__ __forceinline__ f2 ld2(const float* p) {
    f2 r; r.v = *reinterpret_cast<const unsigned long long*>(p); return r;
}
__device__ __forceinline__ void unpack2(f2 a, float& lo, float& hi) {
    unsigned int l, h;
    asm("mov.b64 {%0, %1}, %2;" : "=r"(l), "=r"(h) : "l"(a.v));
    lo = __uint_as_float(l); hi = __uint_as_float(h);
}

// ---- spatial pair-product per path (f32x2 lanes = 2 batch elements) ----
template<int P>
__device__ __forceinline__ void compute_pvals(const f2* a, const f2* b, f2* pv) {
    if constexpr (P == 0) {            // (0,0,0)
        pv[0] = fmul2(a[0], b[0]);
    } else if constexpr (P == 1) {     // (0,1,1)
        pv[0] = fmul2(a[0], b[0]); pv[1] = fmul2(a[0], b[1]); pv[2] = fmul2(a[0], b[2]);
    } else if constexpr (P == 2) {     // (0,2,2)
        #pragma unroll
        for (int s = 0; s < 9; ++s) pv[s] = fmul2(a[0], b[s]);
    } else if constexpr (P == 3) {     // (1,0,1)
        pv[0] = fmul2(a[0], b[0]); pv[1] = fmul2(a[1], b[0]); pv[2] = fmul2(a[2], b[0]);
    } else if constexpr (P == 4) {     // (1,1,2): outer product
        #pragma unroll
        for (int i = 0; i < 3; ++i)
            #pragma unroll
            for (int j = 0; j < 3; ++j) pv[i*3+j] = fmul2(a[i], b[j]);
    } else if constexpr (P == 5) {     // (1,1,0): dot
        pv[0] = ffma2(a[2], b[2], ffma2(a[1], b[1], fmul2(a[0], b[0])));
    } else if constexpr (P == 6) {     // (1,1,1,eps): cross(a,b)
        pv[0] = ffma2(a[1], b[2], fneg2(fmul2(a[2], b[1])));
        pv[1] = ffma2(a[2], b[0], fneg2(fmul2(a[0], b[2])));
        pv[2] = ffma2(a[0], b[1], fneg2(fmul2(a[1], b[0])));
    } else if constexpr (P == 7) {     // (1,2,1)
        #pragma unroll
        for (int e = 0; e < 3; ++e)
            pv[e] = ffma2(a[2], b[e*3+2], ffma2(a[1], b[e*3+1], fmul2(a[0], b[e*3+0])));
    } else if constexpr (P == 8) {     // (1,2,2,eps): cross(a, B2[e,:])
        #pragma unroll
        for (int e = 0; e < 3; ++e) {
            const f2* be = b + e*3;
            pv[e*3+0] = ffma2(a[1], be[2], fneg2(fmul2(a[2], be[1])));
            pv[e*3+1] = ffma2(a[2], be[0], fneg2(fmul2(a[0], be[2])));
            pv[e*3+2] = ffma2(a[0], be[1], fneg2(fmul2(a[1], be[0])));
        }
    } else if constexpr (P == 9) {     // (2,0,2)
        #pragma unroll
        for (int s = 0; s < 9; ++s) pv[s] = fmul2(a[s], b[0]);
    } else if constexpr (P == 10) {    // (2,1,1)
        #pragma unroll
        for (int d = 0; d < 3; ++d)
            pv[d] = ffma2(a[d*3+2], b[2], ffma2(a[d*3+1], b[1], fmul2(a[d*3+0], b[0])));
    } else if constexpr (P == 11) {    // (2,1,2,eps): cross(A2[d,:], b)
        #pragma unroll
        for (int d = 0; d < 3; ++d) {
            const f2* ad = a + d*3;
            pv[d*3+0] = ffma2(ad[1], b[2], fneg2(fmul2(ad[2], b[1])));
            pv[d*3+1] = ffma2(ad[2], b[0], fneg2(fmul2(ad[0], b[2])));
            pv[d*3+2] = ffma2(ad[0], b[1], fneg2(fmul2(ad[1], b[0])));
        }
    } else if constexpr (P == 12) {    // (2,2,2)
        #pragma unroll
        for (int d = 0; d < 3; ++d)
            #pragma unroll
            for (int f = 0; f < 3; ++f)
                pv[d*3+f] = ffma2(a[d*3+2], b[f*3+2],
                            ffma2(a[d*3+1], b[f*3+1], fmul2(a[d*3+0], b[f*3+0])));
    } else if constexpr (P == 13) {    // (2,2,0): full contraction
        f2 s = fmul2(a[0], b[0]);
        #pragma unroll
        for (int t = 1; t < 9; ++t) s = ffma2(a[t], b[t], s);
        pv[0] = s;
    } else {                           // P==14 (2,2,1,eps)
        f2 M[3][3];
        #pragma unroll
        for (int d = 0; d < 3; ++d)
            #pragma unroll
            for (int f = 0; f < 3; ++f)
                M[d][f] = ffma2(a[d*3+2], b[f*3+2],
                          ffma2(a[d*3+1], b[f*3+1], fmul2(a[d*3+0], b[f*3+0])));
        pv[0] = fadd2(M[1][2], fneg2(M[2][1]));
        pv[1] = fadd2(M[2][0], fneg2(M[0][2]));
        pv[2] = fadd2(M[0][1], fneg2(M[1][0]));
    }
}

template<int P>
__device__ __forceinline__ void run_path(
    const float* __restrict__ x1, const float* __restrict__ x2,
    const float* __restrict__ w, int n0,
    float* __restrict__ sOut, float* __restrict__ sB,
    float* __restrict__ sW, float* __restrict__ sA,
    int tid, int cg, int nh)
{
    constexpr int L1 = P_L1[P], L2 = P_L2[P], LO = P_LOUT[P];
    constexpr int R1 = R_[L1], R2 = R_[L2], RO = R_[LO];
    constexpr int OFF1 = OFFS[L1], OFF2 = OFFS[L2];
    constexpr int SLOT = SLOTB[LO];
    constexpr int NF = 64 * R2;           // B-block features
    const float* wp = w + (size_t)P * WSZ;

    // entry barrier: previous path finished reading sB
    __syncthreads();

    // stage B block as packed n-pairs: sB2[f][np] = (x2[2np, f], x2[2np+1, f])
    for (int idx = tid; idx < NF * 16; idx += NTHR) {
        int np = idx / NF;
        int f  = idx - np * NF;
        const float* src = x2 + (size_t)(n0 + 2*np) * FEAT + OFF2 + f;
        *reinterpret_cast<unsigned long long*>(sB + (f * 16 + np) * 2)
            = pack2(src[0], src[FEAT]);
    }

    f2 acc[4][RO];
    #pragma unroll
    for (int cc = 0; cc < 4; ++cc)
        #pragma unroll
        for (int o = 0; o < RO; ++o) acc[cc][o] = fzero2();

    for (int a = 0; a < 64; ++a) {
        __syncthreads();  // prior chunk's sW/sA reads done (and at a=0: sB stores visible)
        // stage W chunk for this a, duplicated (w,w): sW2[c*65+b]
        {
            int c = tid >> 2, q = tid & 3;
            const float* src = wp + (size_t)c * 4096 + (size_t)a * 64 + q * 16;
            float4 v0 = reinterpret_cast<const float4*>(src)[0];
            float4 v1 = reinterpret_cast<const float4*>(src)[1];
            float4 v2 = reinterpret_cast<const float4*>(src)[2];
            float4 v3 = reinterpret_cast<const float4*>(src)[3];
            float buf[16] = {v0.x,v0.y,v0.z,v0.w, v1.x,v1.y,v1.z,v1.w,
                             v2.x,v2.y,v2.z,v2.w, v3.x,v3.y,v3.z,v3.w};
            unsigned long long* dst =
                reinterpret_cast<unsigned long long*>(sW + (c * 65 + q * 16) * 2);
            #pragma unroll
            for (int j = 0; j < 16; ++j) dst[j] = pack2(buf[j], buf[j]);
        }
        // stage A chunk as pairs: sA2[s][np]
        {
            int idx = tid;
            if (idx < 16 * R1) {
                int s = idx >> 4, np = idx & 15;
                const float* src = x1 + (size_t)(n0 + 2*np) * FEAT + OFF1 + a * R1 + s;
                *reinterpret_cast<unsigned long long*>(sA + (s * 16 + np) * 2)
                    = pack2(src[0], src[FEAT]);
            }
        }
        __syncthreads();

        f2 areg[R1];
        #pragma unroll
        for (int s = 0; s < R1; ++s) areg[s] = ld2(sA + (s * 16 + nh) * 2);

        #pragma unroll 4
        for (int b = 0; b < 64; ++b) {
            f2 breg[R2];
            #pragma unroll
            for (int s = 0; s < R2; ++s) breg[s] = ld2(sB + ((b * R2 + s) * 16 + nh) * 2);
            f2 pv[RO];
            compute_pvals<P>(areg, breg, pv);
            #pragma unroll
            for (int cc = 0; cc < 4; ++cc) {
                f2 wv = ld2(sW + ((cg * 4 + cc) * 65 + b) * 2);  // (w,w) broadcast
                #pragma unroll
                for (int o = 0; o < RO; ++o)
                    acc[cc][o] = ffma2(wv, pv[o], acc[cc][o]);
            }
        }
    }

    // merge into smem out accumulators (owner-exclusive (c, n-pair) -> no races)
    #pragma unroll
    for (int cc = 0; cc < 4; ++cc) {
        int c = cg * 4 + cc;
        #pragma unroll
        for (int o = 0; o < RO; ++o) {
            float lo, hi;
            unpack2(acc[cc][o], lo, hi);
            float* p = sOut + (c * 13 + SLOT + o) * NB + 2 * nh;
            p[0] += lo;
            p[1] += hi;
        }
    }
}

__global__ void __launch_bounds__(NTHR, 1)
tp_kernel(const float* __restrict__ x1, const float* __restrict__ x2,
          const float* __restrict__ w, float* __restrict__ out)
{
    extern __shared__ float smem[];
    float* sOut = smem;
    float* sB   = sOut + SZ_OUT;
    float* sW   = sB + SZ_B2;
    float* sA   = sW + SZ_W2;

    const int tid = threadIdx.x;
    const int n0  = blockIdx.x * NB;
    // c-group: 16 groups of 4 channels; each warp splits into two chalf groups
    const int cg  = ((tid >> 5) << 1) | ((tid >> 4) & 1);
    const int nh  = tid & 15;   // n-pair lane: owns batch elems (2nh, 2nh+1)

    for (int i = tid; i < SZ_OUT; i += NTHR) sOut[i] = 0.f;

    run_path< 0>(x1,x2,w,n0,sOut,sB,sW,sA,tid,cg,nh);
    run_path< 1>(x1,x2,w,n0,sOut,sB,sW,sA,tid,cg,nh);
    run_path< 2>(x1,x2,w,n0,sOut,sB,sW,sA,tid,cg,nh);
    run_path< 3>(x1,x2,w,n0,sOut,sB,sW,sA,tid,cg,nh);
    run_path< 4>(x1,x2,w,n0,sOut,sB,sW,sA,tid,cg,nh);
    run_path< 5>(x1,x2,w,n0,sOut,sB,sW,sA,tid,cg,nh);
    run_path< 6>(x1,x2,w,n0,sOut,sB,sW,sA,tid,cg,nh);
    run_path< 7>(x1,x2,w,n0,sOut,sB,sW,sA,tid,cg,nh);
    run_path< 8>(x1,x2,w,n0,sOut,sB,sW,sA,tid,cg,nh);
    run_path< 9>(x1,x2,w,n0,sOut,sB,sW,sA,tid,cg,nh);
    run_path<10>(x1,x2,w,n0,sOut,sB,sW,sA,tid,cg,nh);
    run_path<11>(x1,x2,w,n0,sOut,sB,sW,sA,tid,cg,nh);
    run_path<12>(x1,x2,w,n0,sOut,sB,sW,sA,tid,cg,nh);
    run_path<13>(x1,x2,w,n0,sOut,sB,sW,sA,tid,cg,nh);
    run_path<14>(x1,x2,w,n0,sOut,sB,sW,sA,tid,cg,nh);

    __syncthreads();
    // coalesced writeback: out[n, f], f -> (c, slot)
    for (int i = tid; i < NB * FEAT; i += NTHR) {
        int n = i / FEAT;
        int f = i - n * FEAT;
        int c, slot;
        if (f < 64)       { c = f;                slot = 0; }
        else if (f < 256) { int r = f - 64;  c = r / 3; slot = 1 + (r - c * 3); }
        else              { int r = f - 256; c = r / 9; slot = 4 + (r - c * 9); }
        out[(size_t)(blockIdx.x * NB + n) * FEAT + f] = sOut[(c * 13 + slot) * NB + n];
    }
}

} // namespace

extern "C" void kernel_launch(void* const* d_in, const int* in_sizes, int n_in,
                              void* d_out, int out_size)
{
    const float* x1 = (const float*)d_in[0];
    const float* x2 = (const float*)d_in[1];
    const float* w  = (const float*)d_in[2];
    float* out = (float*)d_out;

    cudaFuncSetAttribute(tp_kernel, cudaFuncAttributeMaxDynamicSharedMemorySize, SMEM_BYTES);
    tp_kernel<<<NBLK, NTHR, SMEM_BYTES>>>(x1, x2, w, out);
}

// round 14
// speedup vs baseline: 1.1907x; 1.1863x over previous
#include <cuda_runtime.h>
#include <cstdint>
#include <cstddef>

namespace {

constexpr int BATCH = 4096;
constexpr int FEAT  = 832;          // 64 * (1+3+9)
constexpr int NB    = 32;           // batch tile per block
constexpr int NBLK  = BATCH / NB;   // 128 blocks
constexpr int NTHR  = 512;          // 16 warps: 2 k-halves x 8 c-groups x 32 lanes
constexpr int WSZ   = 64 * 64 * 64; // weights per path

// path tables: (L1, L2, Lout) in reference enumeration order
constexpr int P_L1[15]   = {0,0,0,1,1,1,1,1,1,2,2,2,2,2,2};
constexpr int P_L2[15]   = {0,1,2,0,1,1,1,2,2,0,1,1,2,2,2};
constexpr int P_LOUT[15] = {0,1,2,1,2,0,1,1,2,2,1,2,2,0,1};

constexpr int OFFS[3]  = {0, 64, 256};  // feature offset of L-block
constexpr int SLOTB[3] = {0, 1, 4};     // out slot base per Lout
constexpr int R_[3]    = {1, 3, 9};     // 3^L

// smem layout (floats)
constexpr int SZ_OUT = 64 * 13 * NB;    // 26624  (out accumulators [c][slot][n])
constexpr int SZ_B   = 576 * 33;        // 19008  (B L2-block, n-stride padded to 33)
constexpr int SZ_W   = 64 * 64;         // 4096   (W chunk [c][b] for fixed a)
constexpr int SZ_A   = 9 * NB;          // 288    (A chunk [sA][n] for fixed a)
constexpr int SMEM_FLOATS = SZ_OUT + SZ_B + SZ_W + SZ_A;   // 50016
constexpr int SMEM_BYTES  = SMEM_FLOATS * 4;               // 200064

// ---- spatial pair-product per path: pv[O] = sum over contracted indices ----
template<int P>
__device__ __forceinline__ void compute_pvals(const float* a, const float* b, float* pv) {
    if constexpr (P == 0) {            // (0,0,0): scalar*scalar
        pv[0] = a[0] * b[0];
    } else if constexpr (P == 1) {     // (0,1,1)
        pv[0] = a[0]*b[0]; pv[1] = a[0]*b[1]; pv[2] = a[0]*b[2];
    } else if constexpr (P == 2) {     // (0,2,2)
        #pragma unroll
        for (int s = 0; s < 9; ++s) pv[s] = a[0]*b[s];
    } else if constexpr (P == 3) {     // (1,0,1)
        pv[0] = a[0]*b[0]; pv[1] = a[1]*b[0]; pv[2] = a[2]*b[0];
    } else if constexpr (P == 4) {     // (1,1,2): outer product
        #pragma unroll
        for (int i = 0; i < 3; ++i)
            #pragma unroll
            for (int j = 0; j < 3; ++j) pv[i*3+j] = a[i]*b[j];
    } else if constexpr (P == 5) {     // (1,1,0): dot
        pv[0] = a[0]*b[0] + a[1]*b[1] + a[2]*b[2];
    } else if constexpr (P == 6) {     // (1,1,1,eps): cross(a,b)
        pv[0] = a[1]*b[2] - a[2]*b[1];
        pv[1] = a[2]*b[0] - a[0]*b[2];
        pv[2] = a[0]*b[1] - a[1]*b[0];
    } else if constexpr (P == 7) {     // (1,2,1): pv[e] = sum_m a[m] B2[e,m]
        #pragma unroll
        for (int e = 0; e < 3; ++e)
            pv[e] = a[0]*b[e*3+0] + a[1]*b[e*3+1] + a[2]*b[e*3+2];
    } else if constexpr (P == 8) {     // (1,2,2,eps): pv[e*3+p] = cross(a, B2[e,:])[p]
        #pragma unroll
        for (int e = 0; e < 3; ++e) {
            const float* be = b + e*3;
            pv[e*3+0] = a[1]*be[2] - a[2]*be[1];
            pv[e*3+1] = a[2]*be[0] - a[0]*be[2];
            pv[e*3+2] = a[0]*be[1] - a[1]*be[0];
        }
    } else if constexpr (P == 9) {     // (2,0,2)
        #pragma unroll
        for (int s = 0; s < 9; ++s) pv[s] = a[s]*b[0];
    } else if constexpr (P == 10) {    // (2,1,1): pv[d] = sum_m A2[d,m] b[m]
        #pragma unroll
        for (int d = 0; d < 3; ++d)
            pv[d] = a[d*3+0]*b[0] + a[d*3+1]*b[1] + a[d*3+2]*b[2];
    } else if constexpr (P == 11) {    // (2,1,2,eps): pv[d*3+p] = cross(A2[d,:], b)[p]
        #pragma unroll
        for (int d = 0; d < 3; ++d) {
            const float* ad = a + d*3;
            pv[d*3+0] = ad[1]*b[2] - ad[2]*b[1];
            pv[d*3+1] = ad[2]*b[0] - ad[0]*b[2];
            pv[d*3+2] = ad[0]*b[1] - ad[1]*b[0];
        }
    } else if constexpr (P == 12) {    // (2,2,2): pv[d*3+f] = sum_m A2[d,m] B2[f,m]
        #pragma unroll
        for (int d = 0; d < 3; ++d)
            #pragma unroll
            for (int f = 0; f < 3; ++f)
                pv[d*3+f] = a[d*3+0]*b[f*3+0] + a[d*3+1]*b[f*3+1] + a[d*3+2]*b[f*3+2];
    } else if constexpr (P == 13) {    // (2,2,0): full contraction
        float s = 0.f;
        #pragma unroll
        for (int t = 0; t < 9; ++t) s = fmaf(a[t], b[t], s);
        pv[0] = s;
    } else {                           // P==14 (2,2,1,eps): M[d,f]=sum_e A2[d,e]B2[f,e]; pv=eps:M
        float M[3][3];
        #pragma unroll
        for (int d = 0; d < 3; ++d)
            #pragma unroll
            for (int f = 0; f < 3; ++f)
                M[d][f] = a[d*3+0]*b[f*3+0] + a[d*3+1]*b[f*3+1] + a[d*3+2]*b[f*3+2];
        pv[0] = M[1][2] - M[2][1];
        pv[1] = M[2][0] - M[0][2];
        pv[2] = M[0][1] - M[1][0];
    }
}

template<int P>
__device__ __forceinline__ void run_path(
    const float* __restrict__ x1, const float* __restrict__ x2,
    const float* __restrict__ w, int n0,
    float* __restrict__ sOut, float* __restrict__ sB,
    float* __restrict__ sW, float* __restrict__ sA,
    int tid, int kh, int cg, int nl)
{
    constexpr int L1 = P_L1[P], L2 = P_L2[P], LO = P_LOUT[P];
    constexpr int R1 = R_[L1], R2 = R_[L2], RO = R_[LO];
    constexpr int OFF1 = OFFS[L1], OFF2 = OFFS[L2];
    constexpr int SLOT = SLOTB[LO];
    constexpr int NF = 64 * R2;           // B-block features
    const float* wp = w + (size_t)P * WSZ;

    // entry barrier: previous path finished reading sB / merging sOut
    __syncthreads();

    // stage B L2-block: sB[f*33 + n] = x2[n0+n, OFF2 + f]   (coalesced global reads)
    for (int idx = tid; idx < NF * NB; idx += NTHR) {
        int n = idx / NF;
        int f = idx - n * NF;
        sB[f * 33 + n] = x2[(size_t)(n0 + n) * FEAT + OFF2 + f];
    }

    float acc[8][RO];
    #pragma unroll
    for (int cc = 0; cc < 8; ++cc)
        #pragma unroll
        for (int o = 0; o < RO; ++o) acc[cc][o] = 0.f;

    const int b0 = kh * 32;   // this half's b range [b0, b0+32)

    for (int a = 0; a < 64; ++a) {
        __syncthreads();  // prior chunk's sW/sA reads done (and at a=0: sB stores visible)
        // stage W chunk for this a: sW[c*64+b] = W[c,a,b]  (512 thr -> 8 floats each)
        {
            int c = tid >> 3, q = tid & 7;
            const float4* src = reinterpret_cast<const float4*>(
                wp + (size_t)c * 4096 + (size_t)a * 64 + q * 8);
            float4* dst = reinterpret_cast<float4*>(sW + c * 64 + q * 8);
            dst[0] = src[0]; dst[1] = src[1];
        }
        // stage A chunk: sA[s*32+n] = A_L1[n, a, s]
        if (tid < NB * R1) {
            int s = tid >> 5, n = tid & 31;
            sA[s * 32 + n] = x1[(size_t)(n0 + n) * FEAT + OFF1 + a * R1 + s];
        }
        __syncthreads();

        float areg[R1];
        #pragma unroll
        for (int s = 0; s < R1; ++s) areg[s] = sA[s * 32 + nl];

        auto body = [&](int b) {
            float breg[R2];
            #pragma unroll
            for (int s = 0; s < R2; ++s) breg[s] = sB[(b * R2 + s) * 33 + nl];
            float pv[RO];
            compute_pvals<P>(areg, breg, pv);
            #pragma unroll
            for (int cc = 0; cc < 8; ++cc) {
                float wv = sW[(cg * 8 + cc) * 64 + b];   // warp-uniform -> LDS broadcast
                #pragma unroll
                for (int o = 0; o < RO; ++o)
                    acc[cc][o] = fmaf(wv, pv[o], acc[cc][o]);
            }
        };

        if constexpr (RO >= 9) {
            #pragma unroll 2
            for (int bi = 0; bi < 32; ++bi) body(b0 + bi);
        } else {
            #pragma unroll 4
            for (int bi = 0; bi < 32; ++bi) body(b0 + bi);
        }
    }

    // merge into smem out accumulators.
    // The two k-halves target the SAME (c, slot, n) cells -> serialize via barrier.
    if (kh == 0) {
        #pragma unroll
        for (int cc = 0; cc < 8; ++cc) {
            int c = cg * 8 + cc;
            #pragma unroll
            for (int o = 0; o < RO; ++o)
                sOut[(c * 13 + SLOT + o) * NB + nl] += acc[cc][o];
        }
    }
    __syncthreads();
    if (kh == 1) {
        #pragma unroll
        for (int cc = 0; cc < 8; ++cc) {
            int c = cg * 8 + cc;
            #pragma unroll
            for (int o = 0; o < RO; ++o)
                sOut[(c * 13 + SLOT + o) * NB + nl] += acc[cc][o];
        }
    }
}

__global__ void __launch_bounds__(NTHR, 1)
tp_kernel(const float* __restrict__ x1, const float* __restrict__ x2,
          const float* __restrict__ w, float* __restrict__ out)
{
    extern __shared__ float smem[];
    float* sOut = smem;
    float* sB   = sOut + SZ_OUT;
    float* sW   = sB + SZ_B;
    float* sA   = sW + SZ_W;

    const int tid = threadIdx.x;
    const int n0  = blockIdx.x * NB;
    const int kh  = tid >> 8;          // k-half: b in [kh*32, kh*32+32)
    const int cg  = (tid >> 5) & 7;    // c-group: thread owns c in [cg*8, cg*8+8)
    const int nl  = tid & 31;          // batch lane

    for (int i = tid; i < SZ_OUT; i += NTHR) sOut[i] = 0.f;

    run_path< 0>(x1,x2,w,n0,sOut,sB,sW,sA,tid,kh,cg,nl);
    run_path< 1>(x1,x2,w,n0,sOut,sB,sW,sA,tid,kh,cg,nl);
    run_path< 2>(x1,x2,w,n0,sOut,sB,sW,sA,tid,kh,cg,nl);
    run_path< 3>(x1,x2,w,n0,sOut,sB,sW,sA,tid,kh,cg,nl);
    run_path< 4>(x1,x2,w,n0,sOut,sB,sW,sA,tid,kh,cg,nl);
    run_path< 5>(x1,x2,w,n0,sOut,sB,sW,sA,tid,kh,cg,nl);
    run_path< 6>(x1,x2,w,n0,sOut,sB,sW,sA,tid,kh,cg,nl);
    run_path< 7>(x1,x2,w,n0,sOut,sB,sW,sA,tid,kh,cg,nl);
    run_path< 8>(x1,x2,w,n0,sOut,sB,sW,sA,tid,kh,cg,nl);
    run_path< 9>(x1,x2,w,n0,sOut,sB,sW,sA,tid,kh,cg,nl);
    run_path<10>(x1,x2,w,n0,sOut,sB,sW,sA,tid,kh,cg,nl);
    run_path<11>(x1,x2,w,n0,sOut,sB,sW,sA,tid,kh,cg,nl);
    run_path<12>(x1,x2,w,n0,sOut,sB,sW,sA,tid,kh,cg,nl);
    run_path<13>(x1,x2,w,n0,sOut,sB,sW,sA,tid,kh,cg,nl);
    run_path<14>(x1,x2,w,n0,sOut,sB,sW,sA,tid,kh,cg,nl);

    __syncthreads();
    // coalesced writeback: out[n, f], f -> (c, slot)
    for (int i = tid; i < NB * FEAT; i += NTHR) {
        int n = i / FEAT;
        int f = i - n * FEAT;
        int c, slot;
        if (f < 64)       { c = f;                slot = 0; }
        else if (f < 256) { int r = f - 64;  c = r / 3; slot = 1 + (r - c * 3); }
        else              { int r = f - 256; c = r / 9; slot = 4 + (r - c * 9); }
        out[(size_t)(n0 + n) * FEAT + f] = sOut[(c * 13 + slot) * NB + n];
    }
}

} // namespace

extern "C" void kernel_launch(void* const* d_in, const int* in_sizes, int n_in,
                              void* d_out, int out_size)
{
    const float* x1 = (const float*)d_in[0];
    const float* x2 = (const float*)d_in[1];
    const float* w  = (const float*)d_in[2];
    float* out = (float*)d_out;

    cudaFuncSetAttribute(tp_kernel, cudaFuncAttributeMaxDynamicSharedMemorySize, SMEM_BYTES);
    tp_kernel<<<NBLK, NTHR, SMEM_BYTES>>>(x1, x2, w, out);
}

// round 17
// speedup vs baseline: 1.1941x; 1.0029x over previous
#include <cuda_runtime.h>
#include <cstdint>
#include <cstddef>

namespace {

constexpr int BATCH = 4096;
constexpr int FEAT  = 832;          // 64 * (1+3+9)
constexpr int NB    = 32;           // batch tile per block
constexpr int NBLK  = BATCH / NB;   // 128 blocks
constexpr int NTHR  = 512;          // 16 warps: 2 k-halves x 8 c-groups x 32 lanes
constexpr int WSZ   = 64 * 64 * 64; // weights per path

// path tables: (L1, L2, Lout) in reference enumeration order
constexpr int P_L1[15]   = {0,0,0,1,1,1,1,1,1,2,2,2,2,2,2};
constexpr int P_L2[15]   = {0,1,2,0,1,1,1,2,2,0,1,1,2,2,2};
constexpr int P_LOUT[15] = {0,1,2,1,2,0,1,1,2,2,1,2,2,0,1};

constexpr int OFFS[3]  = {0, 64, 256};  // feature offset of L-block
constexpr int SLOTB[3] = {0, 1, 4};     // out slot base per Lout
constexpr int R_[3]    = {1, 3, 9};     // 3^L

// smem layout (floats)
constexpr int SZ_OUT = 64 * 13 * NB;    // 26624  (out accumulators [c][slot][n])
constexpr int SZ_B   = 576 * 33;        // 19008  (B L2-block, n-stride padded to 33)
constexpr int SZ_W   = 64 * 64;         // 4096   (W chunk [c][b] for fixed a)
constexpr int SZ_A   = 9 * NB;          // 288    (A chunk [sA][n] for fixed a)
constexpr int SMEM_FLOATS = SZ_OUT + SZ_B + SZ_W + SZ_A;   // 50016
constexpr int SMEM_BYTES  = SMEM_FLOATS * 4;               // 200064

// ---- spatial pair-product per path: pv[O] = sum over contracted indices ----
template<int P>
__device__ __forceinline__ void compute_pvals(const float* a, const float* b, float* pv) {
    if constexpr (P == 0) {            // (0,0,0): scalar*scalar
        pv[0] = a[0] * b[0];
    } else if constexpr (P == 1) {     // (0,1,1)
        pv[0] = a[0]*b[0]; pv[1] = a[0]*b[1]; pv[2] = a[0]*b[2];
    } else if constexpr (P == 2) {     // (0,2,2)
        #pragma unroll
        for (int s = 0; s < 9; ++s) pv[s] = a[0]*b[s];
    } else if constexpr (P == 3) {     // (1,0,1)
        pv[0] = a[0]*b[0]; pv[1] = a[1]*b[0]; pv[2] = a[2]*b[0];
    } else if constexpr (P == 4) {     // (1,1,2): outer product
        #pragma unroll
        for (int i = 0; i < 3; ++i)
            #pragma unroll
            for (int j = 0; j < 3; ++j) pv[i*3+j] = a[i]*b[j];
    } else if constexpr (P == 5) {     // (1,1,0): dot
        pv[0] = a[0]*b[0] + a[1]*b[1] + a[2]*b[2];
    } else if constexpr (P == 6) {     // (1,1,1,eps): cross(a,b)
        pv[0] = a[1]*b[2] - a[2]*b[1];
        pv[1] = a[2]*b[0] - a[0]*b[2];
        pv[2] = a[0]*b[1] - a[1]*b[0];
    } else if constexpr (P == 7) {     // (1,2,1): pv[e] = sum_m a[m] B2[e,m]
        #pragma unroll
        for (int e = 0; e < 3; ++e)
            pv[e] = a[0]*b[e*3+0] + a[1]*b[e*3+1] + a[2]*b[e*3+2];
    } else if constexpr (P == 8) {     // (1,2,2,eps): pv[e*3+p] = cross(a, B2[e,:])[p]
        #pragma unroll
        for (int e = 0; e < 3; ++e) {
            const float* be = b + e*3;
            pv[e*3+0] = a[1]*be[2] - a[2]*be[1];
            pv[e*3+1] = a[2]*be[0] - a[0]*be[2];
            pv[e*3+2] = a[0]*be[1] - a[1]*be[0];
        }
    } else if constexpr (P == 9) {     // (2,0,2)
        #pragma unroll
        for (int s = 0; s < 9; ++s) pv[s] = a[s]*b[0];
    } else if constexpr (P == 10) {    // (2,1,1): pv[d] = sum_m A2[d,m] b[m]
        #pragma unroll
        for (int d = 0; d < 3; ++d)
            pv[d] = a[d*3+0]*b[0] + a[d*3+1]*b[1] + a[d*3+2]*b[2];
    } else if constexpr (P == 11) {    // (2,1,2,eps): pv[d*3+p] = cross(A2[d,:], b)[p]
        #pragma unroll
        for (int d = 0; d < 3; ++d) {
            const float* ad = a + d*3;
            pv[d*3+0] = ad[1]*b[2] - ad[2]*b[1];
            pv[d*3+1] = ad[2]*b[0] - ad[0]*b[2];
            pv[d*3+2] = ad[0]*b[1] - ad[1]*b[0];
        }
    } else if constexpr (P == 12) {    // (2,2,2): pv[d*3+f] = sum_m A2[d,m] B2[f,m]
        #pragma unroll
        for (int d = 0; d < 3; ++d)
            #pragma unroll
            for (int f = 0; f < 3; ++f)
                pv[d*3+f] = a[d*3+0]*b[f*3+0] + a[d*3+1]*b[f*3+1] + a[d*3+2]*b[f*3+2];
    } else if constexpr (P == 13) {    // (2,2,0): full contraction
        float s = 0.f;
        #pragma unroll
        for (int t = 0; t < 9; ++t) s = fmaf(a[t], b[t], s);
        pv[0] = s;
    } else {                           // P==14 (2,2,1,eps): M[d,f]=sum_e A2[d,e]B2[f,e]; pv=eps:M
        float M[3][3];
        #pragma unroll
        for (int d = 0; d < 3; ++d)
            #pragma unroll
            for (int f = 0; f < 3; ++f)
                M[d][f] = a[d*3+0]*b[f*3+0] + a[d*3+1]*b[f*3+1] + a[d*3+2]*b[f*3+2];
        pv[0] = M[1][2] - M[2][1];
        pv[1] = M[2][0] - M[0][2];
        pv[2] = M[0][1] - M[1][0];
    }
}

template<int P>
__device__ __forceinline__ void run_path(
    const float* __restrict__ x1, const float* __restrict__ x2,
    const float* __restrict__ w, int n0,
    float* __restrict__ sOut, float* __restrict__ sB,
    float* __restrict__ sW, float* __restrict__ sA,
    int tid, int kh, int cg, int nl)
{
    constexpr int L1 = P_L1[P], L2 = P_L2[P], LO = P_LOUT[P];
    constexpr int R1 = R_[L1], R2 = R_[L2], RO = R_[LO];
    constexpr int OFF1 = OFFS[L1], OFF2 = OFFS[L2];
    constexpr int SLOT = SLOTB[LO];
    constexpr int NF = 64 * R2;           // B-block features
    const float* wp = w + (size_t)P * WSZ;

    // entry barrier: previous path finished reading sB / merging sOut
    __syncthreads();

    // stage B L2-block: sB[f*33 + n] = x2[n0+n, OFF2 + f]   (coalesced global reads)
    for (int idx = tid; idx < NF * NB; idx += NTHR) {
        int n = idx / NF;
        int f = idx - n * NF;
        sB[f * 33 + n] = x2[(size_t)(n0 + n) * FEAT + OFF2 + f];
    }

    float acc[8][RO];
    #pragma unroll
    for (int cc = 0; cc < 8; ++cc)
        #pragma unroll
        for (int o = 0; o < RO; ++o) acc[cc][o] = 0.f;

    const int b0 = kh * 32;   // this half's b range [b0, b0+32)

    for (int a = 0; a < 64; ++a) {
        __syncthreads();  // prior chunk's sW/sA reads done (and at a=0: sB stores visible)
        // stage W chunk for this a: sW[c*64+b] = W[c,a,b]  (512 thr -> 8 floats each)
        {
            int c = tid >> 3, q = tid & 7;
            const float4* src = reinterpret_cast<const float4*>(
                wp + (size_t)c * 4096 + (size_t)a * 64 + q * 8);
            float4* dst = reinterpret_cast<float4*>(sW + c * 64 + q * 8);
            dst[0] = src[0]; dst[1] = src[1];
        }
        // stage A chunk: sA[s*32+n] = A_L1[n, a, s]
        if (tid < NB * R1) {
            int s = tid >> 5, n = tid & 31;
            sA[s * 32 + n] = x1[(size_t)(n0 + n) * FEAT + OFF1 + a * R1 + s];
        }
        __syncthreads();

        float areg[R1];
        #pragma unroll
        for (int s = 0; s < R1; ++s) areg[s] = sA[s * 32 + nl];

        auto body = [&](int b) {
            float breg[R2];
            #pragma unroll
            for (int s = 0; s < R2; ++s) breg[s] = sB[(b * R2 + s) * 33 + nl];
            float pv[RO];
            compute_pvals<P>(areg, breg, pv);
            #pragma unroll
            for (int cc = 0; cc < 8; ++cc) {
                float wv = sW[(cg * 8 + cc) * 64 + b];   // warp-uniform -> LDS broadcast
                #pragma unroll
                for (int o = 0; o < RO; ++o)
                    acc[cc][o] = fmaf(wv, pv[o], acc[cc][o]);
            }
        };

        if constexpr (RO >= 9) {
            #pragma unroll 2
            for (int bi = 0; bi < 32; ++bi) body(b0 + bi);
        } else {
            #pragma unroll 4
            for (int bi = 0; bi < 32; ++bi) body(b0 + bi);
        }
    }

    // merge into smem out accumulators.
    // The two k-halves target the SAME (c, slot, n) cells -> serialize via barrier.
    if (kh == 0) {
        #pragma unroll
        for (int cc = 0; cc < 8; ++cc) {
            int c = cg * 8 + cc;
            #pragma unroll
            for (int o = 0; o < RO; ++o)
                sOut[(c * 13 + SLOT + o) * NB + nl] += acc[cc][o];
        }
    }
    __syncthreads();
    if (kh == 1) {
        #pragma unroll
        for (int cc = 0; cc < 8; ++cc) {
            int c = cg * 8 + cc;
            #pragma unroll
            for (int o = 0; o < RO; ++o)
                sOut[(c * 13 + SLOT + o) * NB + nl] += acc[cc][o];
        }
    }
}

__global__ void __launch_bounds__(NTHR, 1)
tp_kernel(const float* __restrict__ x1, const float* __restrict__ x2,
          const float* __restrict__ w, float* __restrict__ out)
{
    extern __shared__ float smem[];
    float* sOut = smem;
    float* sB   = sOut + SZ_OUT;
    float* sW   = sB + SZ_B;
    float* sA   = sW + SZ_W;

    const int tid = threadIdx.x;
    const int n0  = blockIdx.x * NB;
    const int kh  = tid >> 8;          // k-half: b in [kh*32, kh*32+32)
    const int cg  = (tid >> 5) & 7;    // c-group: thread owns c in [cg*8, cg*8+8)
    const int nl  = tid & 31;          // batch lane

    for (int i = tid; i < SZ_OUT; i += NTHR) sOut[i] = 0.f;

    run_path< 0>(x1,x2,w,n0,sOut,sB,sW,sA,tid,kh,cg,nl);
    run_path< 1>(x1,x2,w,n0,sOut,sB,sW,sA,tid,kh,cg,nl);
    run_path< 2>(x1,x2,w,n0,sOut,sB,sW,sA,tid,kh,cg,nl);
    run_path< 3>(x1,x2,w,n0,sOut,sB,sW,sA,tid,kh,cg,nl);
    run_path< 4>(x1,x2,w,n0,sOut,sB,sW,sA,tid,kh,cg,nl);
    run_path< 5>(x1,x2,w,n0,sOut,sB,sW,sA,tid,kh,cg,nl);
    run_path< 6>(x1,x2,w,n0,sOut,sB,sW,sA,tid,kh,cg,nl);
    run_path< 7>(x1,x2,w,n0,sOut,sB,sW,sA,tid,kh,cg,nl);
    run_path< 8>(x1,x2,w,n0,sOut,sB,sW,sA,tid,kh,cg,nl);
    run_path< 9>(x1,x2,w,n0,sOut,sB,sW,sA,tid,kh,cg,nl);
    run_path<10>(x1,x2,w,n0,sOut,sB,sW,sA,tid,kh,cg,nl);
    run_path<11>(x1,x2,w,n0,sOut,sB,sW,sA,tid,kh,cg,nl);
    run_path<12>(x1,x2,w,n0,sOut,sB,sW,sA,tid,kh,cg,nl);
    run_path<13>(x1,x2,w,n0,sOut,sB,sW,sA,tid,kh,cg,nl);
    run_path<14>(x1,x2,w,n0,sOut,sB,sW,sA,tid,kh,cg,nl);

    __syncthreads();
    // coalesced writeback: out[n, f], f -> (c, slot)
    for (int i = tid; i < NB * FEAT; i += NTHR) {
        int n = i / FEAT;
        int f = i - n * FEAT;
        int c, slot;
        if (f < 64)       { c = f;                slot = 0; }
        else if (f < 256) { int r = f - 64;  c = r / 3; slot = 1 + (r - c * 3); }
        else              { int r = f - 256; c = r / 9; slot = 4 + (r - c * 9); }
        out[(size_t)(n0 + n) * FEAT + f] = sOut[(c * 13 + slot) * NB + n];
    }
}

} // namespace

extern "C" void kernel_launch(void* const* d_in, const int* in_sizes, int n_in,
                              void* d_out, int out_size)
{
    const float* x1 = (const float*)d_in[0];
    const float* x2 = (const float*)d_in[1];
    const float* w  = (const float*)d_in[2];
    float* out = (float*)d_out;

    cudaFuncSetAttribute(tp_kernel, cudaFuncAttributeMaxDynamicSharedMemorySize, SMEM_BYTES);
    tp_kernel<<<NBLK, NTHR, SMEM_BYTES>>>(x1, x2, w, out);
}